// round 1
// baseline (speedup 1.0000x reference)
#include <cuda_runtime.h>
#include <cuda_bf16.h>

#define NTHREADS 128
#define RPT 4
#define PFEAT 32

// ---- shared-memory layout (floats) ----
#define OFF_WB1 0        // 64x32 (zero-padded col p)
#define OFF_WB2 2048     // 32x64
#define OFF_WB3 4096     // 32x32
#define OFF_WB4 5120     // 16x32
#define OFF_WB5 5632     // 8x16
#define OFF_WB6 5760     // 8
#define OFF_BB1 5768     // 64
#define OFF_BB2 5832     // 32
#define OFF_BB3 5864     // 32
#define OFF_BB4 5896     // 16
#define OFF_BB5 5912     // 8
#define OFF_BB6 5920     // 1 (+pad)
#define OFF_WA1 5924     // 64
#define OFF_BA1 5988     // 64
#define OFF_WA2 6052     // 32x64
#define OFF_BA2 8100     // 32
#define OFF_WA3 8132     // 16x32
#define OFF_BA3 8644     // 16
#define OFF_WA4 8660     // 8x16
#define OFF_BA4 8788     // 8
#define OFF_WA5 8796     // 8
#define OFF_BA5 8804     // 1
#define SMEM_TOT 8808

__device__ __forceinline__ float fast_tanh(float x) {
    float e = __expf(2.0f * x);
    return 1.0f - __fdividef(2.0f, e + 1.0f);
}

// ACT: 0 = none, 1 = relu, 2 = tanh
template<int IN, int OUT, int ACT>
__device__ __forceinline__ void layer(const float* __restrict__ W,
                                      const float* __restrict__ B,
                                      const float* in, float* out) {
#pragma unroll
    for (int o = 0; o < OUT; o += 4) {
        float a0 = B[o + 0], a1 = B[o + 1], a2 = B[o + 2], a3 = B[o + 3];
        const float* w0 = W + (o + 0) * IN;
        const float* w1 = W + (o + 1) * IN;
        const float* w2 = W + (o + 2) * IN;
        const float* w3 = W + (o + 3) * IN;
#pragma unroll
        for (int i = 0; i < IN; i++) {
            float xi = in[i];
            a0 = fmaf(w0[i], xi, a0);
            a1 = fmaf(w1[i], xi, a1);
            a2 = fmaf(w2[i], xi, a2);
            a3 = fmaf(w3[i], xi, a3);
        }
        if (ACT == 1) {
            a0 = fmaxf(a0, 0.0f); a1 = fmaxf(a1, 0.0f);
            a2 = fmaxf(a2, 0.0f); a3 = fmaxf(a3, 0.0f);
        }
        if (ACT == 2) {
            a0 = fast_tanh(a0); a1 = fast_tanh(a1);
            a2 = fast_tanh(a2); a3 = fast_tanh(a3);
        }
        out[o + 0] = a0; out[o + 1] = a1; out[o + 2] = a2; out[o + 3] = a3;
    }
}

template<int IN>
__device__ __forceinline__ float dotb(const float* __restrict__ W, float b,
                                      const float* in) {
    float a = b;
#pragma unroll
    for (int i = 0; i < IN; i++) a = fmaf(W[i], in[i], a);
    return a;
}

__device__ __forceinline__ void cpy(float* dst, const float* __restrict__ src,
                                    int n, int tid) {
    for (int i = tid; i < n; i += NTHREADS) dst[i] = src[i];
}

__global__ void __launch_bounds__(NTHREADS)
mlp32_kernel(const float* __restrict__ x,
             const float* __restrict__ Wa1, const float* __restrict__ ba1,
             const float* __restrict__ Wa2, const float* __restrict__ ba2,
             const float* __restrict__ Wa3, const float* __restrict__ ba3,
             const float* __restrict__ Wa4, const float* __restrict__ ba4,
             const float* __restrict__ Wa5, const float* __restrict__ ba5,
             const float* __restrict__ Wb1, const float* __restrict__ bb1,
             const float* __restrict__ Wb2, const float* __restrict__ bb2,
             const float* __restrict__ Wb3, const float* __restrict__ bb3,
             const float* __restrict__ Wb4, const float* __restrict__ bb4,
             const float* __restrict__ Wb5, const float* __restrict__ bb5,
             const float* __restrict__ Wb6, const float* __restrict__ bb6,
             float* __restrict__ out, int nrows) {
    __shared__ float s[SMEM_TOT];
    const int p = blockIdx.y;
    const int tid = threadIdx.x;

    // ---- stage weights for feature p into smem ----
    // Wb1: [P][64][31] -> padded [64][32] with column p zeroed
    for (int i = tid; i < 64 * 32; i += NTHREADS) {
        int o = i >> 5, j = i & 31;
        float v = 0.0f;
        if (j < p)      v = Wb1[(p * 64 + o) * 31 + j];
        else if (j > p) v = Wb1[(p * 64 + o) * 31 + j - 1];
        s[OFF_WB1 + i] = v;
    }
    cpy(s + OFF_WB2, Wb2 + p * 32 * 64, 32 * 64, tid);
    cpy(s + OFF_WB3, Wb3 + p * 32 * 32, 32 * 32, tid);
    cpy(s + OFF_WB4, Wb4 + p * 16 * 32, 16 * 32, tid);
    cpy(s + OFF_WB5, Wb5 + p * 8 * 16,  8 * 16,  tid);
    cpy(s + OFF_WB6, Wb6 + p * 8,       8,       tid);
    cpy(s + OFF_BB1, bb1 + p * 64,      64,      tid);
    cpy(s + OFF_BB2, bb2 + p * 32,      32,      tid);
    cpy(s + OFF_BB3, bb3 + p * 32,      32,      tid);
    cpy(s + OFF_BB4, bb4 + p * 16,      16,      tid);
    cpy(s + OFF_BB5, bb5 + p * 8,       8,       tid);
    cpy(s + OFF_WA1, Wa1 + p * 64,      64,      tid);
    cpy(s + OFF_BA1, ba1 + p * 64,      64,      tid);
    cpy(s + OFF_WA2, Wa2 + p * 32 * 64, 32 * 64, tid);
    cpy(s + OFF_BA2, ba2 + p * 32,      32,      tid);
    cpy(s + OFF_WA3, Wa3 + p * 16 * 32, 16 * 32, tid);
    cpy(s + OFF_BA3, ba3 + p * 16,      16,      tid);
    cpy(s + OFF_WA4, Wa4 + p * 8 * 16,  8 * 16,  tid);
    cpy(s + OFF_BA4, ba4 + p * 8,       8,       tid);
    cpy(s + OFF_WA5, Wa5 + p * 8,       8,       tid);
    if (tid == 0) {
        s[OFF_BB6] = bb6[p];
        s[OFF_BA5] = ba5[p];
    }
    __syncthreads();

    const int base = blockIdx.x * (NTHREADS * RPT) + tid;

    for (int r = 0; r < RPT; ++r) {
        const int row = base + r * NTHREADS;
        if (row >= nrows) break;

        // load row of x (coalesced float4)
        float xr[32];
        const float4* xv = reinterpret_cast<const float4*>(x) + row * 8;
#pragma unroll
        for (int q = 0; q < 8; q++) {
            float4 v = xv[q];
            xr[4 * q + 0] = v.x; xr[4 * q + 1] = v.y;
            xr[4 * q + 2] = v.z; xr[4 * q + 3] = v.w;
        }
        const float xs = x[row * 32 + p];  // scalar input for encoder A

        // ---- encoder B: 32(padded) ->64 relu ->32 tanh ->32 tanh ->16 tanh ->8 ->1 ----
        float h1[64];
        layer<32, 64, 1>(s + OFF_WB1, s + OFF_BB1, xr, h1);
        float h2[32];
        layer<64, 32, 2>(s + OFF_WB2, s + OFF_BB2, h1, h2);
        float h3[32];
        layer<32, 32, 2>(s + OFF_WB3, s + OFF_BB3, h2, h3);
        float h4[16];
        layer<32, 16, 2>(s + OFF_WB4, s + OFF_BB4, h3, h4);
        float h5[8];
        layer<16, 8, 0>(s + OFF_WB5, s + OFF_BB5, h4, h5);
        const float bOut = dotb<8>(s + OFF_WB6, s[OFF_BB6], h5);

        // ---- encoder A: 1 ->64 relu ->32 tanh ->16 tanh ->8 tanh ->1 ----
        float a1[64];
#pragma unroll
        for (int o = 0; o < 64; o++)
            a1[o] = fmaxf(fmaf(s[OFF_WA1 + o], xs, s[OFF_BA1 + o]), 0.0f);
        float a2[32];
        layer<64, 32, 2>(s + OFF_WA2, s + OFF_BA2, a1, a2);
        float a3[16];
        layer<32, 16, 2>(s + OFF_WA3, s + OFF_BA3, a2, a3);
        float a4[8];
        layer<16, 8, 2>(s + OFF_WA4, s + OFF_BA4, a3, a4);
        const float aOut = dotb<8>(s + OFF_WA5, s[OFF_BA5], a4);

        out[row * 64 + 2 * p + 0] = aOut;
        out[row * 64 + 2 * p + 1] = bOut;
    }
}

extern "C" void kernel_launch(void* const* d_in, const int* in_sizes, int n_in,
                              void* d_out, int out_size) {
    const float* x   = (const float*)d_in[0];
    const float* Wa1 = (const float*)d_in[1];
    const float* ba1 = (const float*)d_in[2];
    const float* Wa2 = (const float*)d_in[3];
    const float* ba2 = (const float*)d_in[4];
    const float* Wa3 = (const float*)d_in[5];
    const float* ba3 = (const float*)d_in[6];
    const float* Wa4 = (const float*)d_in[7];
    const float* ba4 = (const float*)d_in[8];
    const float* Wa5 = (const float*)d_in[9];
    const float* ba5 = (const float*)d_in[10];
    const float* Wb1 = (const float*)d_in[11];
    const float* bb1 = (const float*)d_in[12];
    const float* Wb2 = (const float*)d_in[13];
    const float* bb2 = (const float*)d_in[14];
    const float* Wb3 = (const float*)d_in[15];
    const float* bb3 = (const float*)d_in[16];
    const float* Wb4 = (const float*)d_in[17];
    const float* bb4 = (const float*)d_in[18];
    const float* Wb5 = (const float*)d_in[19];
    const float* bb5 = (const float*)d_in[20];
    const float* Wb6 = (const float*)d_in[21];
    const float* bb6 = (const float*)d_in[22];
    float* out = (float*)d_out;

    const int nrows = in_sizes[0] / PFEAT;
    dim3 grid((nrows + NTHREADS * RPT - 1) / (NTHREADS * RPT), PFEAT);
    mlp32_kernel<<<grid, NTHREADS>>>(
        x, Wa1, ba1, Wa2, ba2, Wa3, ba3, Wa4, ba4, Wa5, ba5,
        Wb1, bb1, Wb2, bb2, Wb3, bb3, Wb4, bb4, Wb5, bb5, Wb6, bb6,
        out, nrows);
}

// round 2
// speedup vs baseline: 1.3818x; 1.3818x over previous
#include <cuda_runtime.h>
#include <cuda_bf16.h>

#define NTHREADS 128
#define RPT 4
#define PFEAT 32

// ---- shared-memory layout (floats), all W/B offsets 16B-aligned ----
// transposed weights: Wt[i][o] = W[o][i]
#define OFF_WB1T 0        // [32][64] (input-row p zeroed)
#define OFF_WB2T 2048     // [64][32]
#define OFF_WB3T 4096     // [32][32]
#define OFF_WB4T 5120     // [32][16]
#define OFF_WB5T 5632     // [16][8]
#define OFF_WA2T 5760     // [64][32]
#define OFF_WA3T 7808     // [32][16]
#define OFF_WA4T 8320     // [16][8]
#define OFF_WA1  8448     // 64
#define OFF_BA1  8512     // 64
#define OFF_BB1  8576     // 64
#define OFF_BB2  8640     // 32
#define OFF_BB3  8672     // 32
#define OFF_BB4  8704     // 16
#define OFF_BA2  8720     // 32
#define OFF_BA3  8752     // 16
#define OFF_BA4  8768     // 8
#define OFF_BB5  8776     // 8
#define OFF_WB6  8784     // 8
#define OFF_WA5  8792     // 8
#define OFF_BB6  8800     // 1
#define OFF_BA5  8801     // 1
#define SMEM_TOT 8804

__device__ __forceinline__ float fast_tanh(float x) {
    float e = __expf(2.0f * x);
    return 1.0f - __fdividef(2.0f, e + 1.0f);
}

// ACT: 0 = none, 1 = relu, 2 = tanh.  Wt is [IN][OUT] (transposed), broadcast LDS.128.
template<int IN, int OUT, int ACT>
__device__ __forceinline__ void layer_t(const float* __restrict__ Wt,
                                        const float* __restrict__ B,
                                        const float* in, float* out) {
    float acc[OUT];
#pragma unroll
    for (int o = 0; o < OUT; o += 4) {
        float4 b4 = *reinterpret_cast<const float4*>(B + o);
        acc[o + 0] = b4.x; acc[o + 1] = b4.y; acc[o + 2] = b4.z; acc[o + 3] = b4.w;
    }
#pragma unroll
    for (int i = 0; i < IN; i++) {
        const float xi = in[i];
#pragma unroll
        for (int o = 0; o < OUT; o += 4) {
            float4 w = *reinterpret_cast<const float4*>(Wt + i * OUT + o);
            acc[o + 0] = fmaf(w.x, xi, acc[o + 0]);
            acc[o + 1] = fmaf(w.y, xi, acc[o + 1]);
            acc[o + 2] = fmaf(w.z, xi, acc[o + 2]);
            acc[o + 3] = fmaf(w.w, xi, acc[o + 3]);
        }
    }
#pragma unroll
    for (int o = 0; o < OUT; o++) {
        float a = acc[o];
        if (ACT == 1) a = fmaxf(a, 0.0f);
        if (ACT == 2) a = fast_tanh(a);
        out[o] = a;
    }
}

// final 8 -> 1 dot, vectorized weight load
__device__ __forceinline__ float dot8(const float* __restrict__ W, float b,
                                      const float* in) {
    float4 w0 = *reinterpret_cast<const float4*>(W);
    float4 w1 = *reinterpret_cast<const float4*>(W + 4);
    float a = b;
    a = fmaf(w0.x, in[0], a); a = fmaf(w0.y, in[1], a);
    a = fmaf(w0.z, in[2], a); a = fmaf(w0.w, in[3], a);
    a = fmaf(w1.x, in[4], a); a = fmaf(w1.y, in[5], a);
    a = fmaf(w1.z, in[6], a); a = fmaf(w1.w, in[7], a);
    return a;
}

__device__ __forceinline__ void cpy(float* dst, const float* __restrict__ src,
                                    int n, int tid) {
    for (int i = tid; i < n; i += NTHREADS) dst[i] = src[i];
}

// stage W [OUT][IN] from gmem into smem transposed as [IN][OUT]
template<int IN, int OUT>
__device__ __forceinline__ void stage_t(float* dst, const float* __restrict__ src,
                                        int tid) {
    for (int idx = tid; idx < IN * OUT; idx += NTHREADS) {
        int i = idx / OUT;          // OUT is a power of 2 -> shift
        int o = idx & (OUT - 1);
        dst[idx] = src[o * IN + i];
    }
}

__global__ void __launch_bounds__(NTHREADS)
mlp32_kernel(const float* __restrict__ x,
             const float* __restrict__ Wa1, const float* __restrict__ ba1,
             const float* __restrict__ Wa2, const float* __restrict__ ba2,
             const float* __restrict__ Wa3, const float* __restrict__ ba3,
             const float* __restrict__ Wa4, const float* __restrict__ ba4,
             const float* __restrict__ Wa5, const float* __restrict__ ba5,
             const float* __restrict__ Wb1, const float* __restrict__ bb1,
             const float* __restrict__ Wb2, const float* __restrict__ bb2,
             const float* __restrict__ Wb3, const float* __restrict__ bb3,
             const float* __restrict__ Wb4, const float* __restrict__ bb4,
             const float* __restrict__ Wb5, const float* __restrict__ bb5,
             const float* __restrict__ Wb6, const float* __restrict__ bb6,
             float* __restrict__ out, int nrows) {
    __shared__ float s[SMEM_TOT];
    const int p = blockIdx.y;
    const int tid = threadIdx.x;

    // ---- stage weights for feature p into smem (transposed) ----
    // Wb1: src [64][31] -> dst [32][64] with input-row p zeroed
    for (int idx = tid; idx < 32 * 64; idx += NTHREADS) {
        int i = idx >> 6, o = idx & 63;
        float v = 0.0f;
        if (i < p)      v = Wb1[(p * 64 + o) * 31 + i];
        else if (i > p) v = Wb1[(p * 64 + o) * 31 + i - 1];
        s[OFF_WB1T + idx] = v;
    }
    stage_t<64, 32>(s + OFF_WB2T, Wb2 + p * 32 * 64, tid);
    stage_t<32, 32>(s + OFF_WB3T, Wb3 + p * 32 * 32, tid);
    stage_t<32, 16>(s + OFF_WB4T, Wb4 + p * 16 * 32, tid);
    stage_t<16, 8>(s + OFF_WB5T, Wb5 + p * 8 * 16, tid);
    stage_t<64, 32>(s + OFF_WA2T, Wa2 + p * 32 * 64, tid);
    stage_t<32, 16>(s + OFF_WA3T, Wa3 + p * 16 * 32, tid);
    stage_t<16, 8>(s + OFF_WA4T, Wa4 + p * 8 * 16, tid);
    cpy(s + OFF_WA1, Wa1 + p * 64, 64, tid);
    cpy(s + OFF_BA1, ba1 + p * 64, 64, tid);
    cpy(s + OFF_BB1, bb1 + p * 64, 64, tid);
    cpy(s + OFF_BB2, bb2 + p * 32, 32, tid);
    cpy(s + OFF_BB3, bb3 + p * 32, 32, tid);
    cpy(s + OFF_BB4, bb4 + p * 16, 16, tid);
    cpy(s + OFF_BA2, ba2 + p * 32, 32, tid);
    cpy(s + OFF_BA3, ba3 + p * 16, 16, tid);
    cpy(s + OFF_BA4, ba4 + p * 8, 8, tid);
    cpy(s + OFF_BB5, bb5 + p * 8, 8, tid);
    cpy(s + OFF_WB6, Wb6 + p * 8, 8, tid);
    cpy(s + OFF_WA5, Wa5 + p * 8, 8, tid);
    if (tid == 0) {
        s[OFF_BB6] = bb6[p];
        s[OFF_BA5] = ba5[p];
    }
    __syncthreads();

    const int base = blockIdx.x * (NTHREADS * RPT) + tid;

#pragma unroll 1
    for (int r = 0; r < RPT; ++r) {
        const int row = base + r * NTHREADS;
        if (row >= nrows) break;

        // load row of x (coalesced float4)
        float xr[32];
        const float4* xv = reinterpret_cast<const float4*>(x) + row * 8;
#pragma unroll
        for (int q = 0; q < 8; q++) {
            float4 v = xv[q];
            xr[4 * q + 0] = v.x; xr[4 * q + 1] = v.y;
            xr[4 * q + 2] = v.z; xr[4 * q + 3] = v.w;
        }
        const float xs = x[row * 32 + p];  // scalar input for encoder A

        // ---- encoder B: 32(padded)->64 relu ->32 tanh ->32 tanh ->16 tanh ->8 ->1 ----
        float h1[64];
        layer_t<32, 64, 1>(s + OFF_WB1T, s + OFF_BB1, xr, h1);
        float h2[32];
        layer_t<64, 32, 2>(s + OFF_WB2T, s + OFF_BB2, h1, h2);
        float h3[32];
        layer_t<32, 32, 2>(s + OFF_WB3T, s + OFF_BB3, h2, h3);
        float h4[16];
        layer_t<32, 16, 2>(s + OFF_WB4T, s + OFF_BB4, h3, h4);
        float h5[8];
        layer_t<16, 8, 0>(s + OFF_WB5T, s + OFF_BB5, h4, h5);
        const float bOut = dot8(s + OFF_WB6, s[OFF_BB6], h5);

        // ---- encoder A: 1 ->64 relu ->32 tanh ->16 tanh ->8 tanh ->1 ----
        float a1[64];
#pragma unroll
        for (int o = 0; o < 64; o += 4) {
            float4 w = *reinterpret_cast<const float4*>(s + OFF_WA1 + o);
            float4 b = *reinterpret_cast<const float4*>(s + OFF_BA1 + o);
            a1[o + 0] = fmaxf(fmaf(w.x, xs, b.x), 0.0f);
            a1[o + 1] = fmaxf(fmaf(w.y, xs, b.y), 0.0f);
            a1[o + 2] = fmaxf(fmaf(w.z, xs, b.z), 0.0f);
            a1[o + 3] = fmaxf(fmaf(w.w, xs, b.w), 0.0f);
        }
        float a2[32];
        layer_t<64, 32, 2>(s + OFF_WA2T, s + OFF_BA2, a1, a2);
        float a3[16];
        layer_t<32, 16, 2>(s + OFF_WA3T, s + OFF_BA3, a2, a3);
        float a4[8];
        layer_t<16, 8, 2>(s + OFF_WA4T, s + OFF_BA4, a3, a4);
        const float aOut = dot8(s + OFF_WA5, s[OFF_BA5], a4);

        out[row * 64 + 2 * p + 0] = aOut;
        out[row * 64 + 2 * p + 1] = bOut;
    }
}

extern "C" void kernel_launch(void* const* d_in, const int* in_sizes, int n_in,
                              void* d_out, int out_size) {
    const float* x   = (const float*)d_in[0];
    const float* Wa1 = (const float*)d_in[1];
    const float* ba1 = (const float*)d_in[2];
    const float* Wa2 = (const float*)d_in[3];
    const float* ba2 = (const float*)d_in[4];
    const float* Wa3 = (const float*)d_in[5];
    const float* ba3 = (const float*)d_in[6];
    const float* Wa4 = (const float*)d_in[7];
    const float* ba4 = (const float*)d_in[8];
    const float* Wa5 = (const float*)d_in[9];
    const float* ba5 = (const float*)d_in[10];
    const float* Wb1 = (const float*)d_in[11];
    const float* bb1 = (const float*)d_in[12];
    const float* Wb2 = (const float*)d_in[13];
    const float* bb2 = (const float*)d_in[14];
    const float* Wb3 = (const float*)d_in[15];
    const float* bb3 = (const float*)d_in[16];
    const float* Wb4 = (const float*)d_in[17];
    const float* bb4 = (const float*)d_in[18];
    const float* Wb5 = (const float*)d_in[19];
    const float* bb5 = (const float*)d_in[20];
    const float* Wb6 = (const float*)d_in[21];
    const float* bb6 = (const float*)d_in[22];
    float* out = (float*)d_out;

    const int nrows = in_sizes[0] / PFEAT;
    dim3 grid((nrows + NTHREADS * RPT - 1) / (NTHREADS * RPT), PFEAT);
    mlp32_kernel<<<grid, NTHREADS>>>(
        x, Wa1, ba1, Wa2, ba2, Wa3, ba3, Wa4, ba4, Wa5, ba5,
        Wb1, bb1, Wb2, bb2, Wb3, bb3, Wb4, bb4, Wb5, bb5, Wb6, bb6,
        out, nrows);
}

// round 3
// speedup vs baseline: 1.7786x; 1.2872x over previous
#include <cuda_runtime.h>
#include <cuda_bf16.h>
#include <cstdint>

#define NTHREADS 128
#define RPT 4
#define PFEAT 32

typedef unsigned long long u64;

// ---- shared-memory layout (floats); all weight bases 16B-aligned, biases 8B ----
#define OFF_WB1T 0        // [32][64] (input-row p zeroed)
#define OFF_WB2T 2048     // [64][32]
#define OFF_WB3T 4096     // [32][32]
#define OFF_WB4T 5120     // [32][16]
#define OFF_WB5T 5632     // [16][8]
#define OFF_WA2T 5760     // [64][32]
#define OFF_WA3T 7808     // [32][16]
#define OFF_WA4T 8320     // [16][8]
#define OFF_WA1  8448     // 64
#define OFF_BA1  8512     // 64
#define OFF_BB1  8576     // 64
#define OFF_BB2  8640     // 32
#define OFF_BB3  8672     // 32
#define OFF_BB4  8704     // 16
#define OFF_BA2  8720     // 32
#define OFF_BA3  8752     // 16
#define OFF_BA4  8768     // 8
#define OFF_BB5  8776     // 8
#define OFF_WB6  8784     // 8
#define OFF_WA5  8792     // 8
#define OFF_BB6  8800     // 1
#define OFF_BA5  8804     // 1  (8B-aligned slots)
#define SMEM_TOT 8808

// ---- f32x2 packed helpers ----
__device__ __forceinline__ u64 pk2(float v) {
    u64 r; asm("mov.b64 %0, {%1, %1};" : "=l"(r) : "f"(v)); return r;
}
__device__ __forceinline__ void upk(float& lo, float& hi, u64 v) {
    asm("mov.b64 {%0, %1}, %2;" : "=f"(lo), "=f"(hi) : "l"(v));
}
__device__ __forceinline__ u64 f2fma(u64 a, u64 b, u64 c) {
    u64 d; asm("fma.rn.f32x2 %0, %1, %2, %3;" : "=l"(d) : "l"(a), "l"(b), "l"(c));
    return d;
}

__device__ __forceinline__ float fast_tanh(float x) {
    float e = __expf(2.0f * x);
    return 1.0f - __fdividef(2.0f, e + 1.0f);
}

// ACT: 0 none, 1 relu, 2 tanh.  Wt [IN][OUT] transposed in smem.
// Processes TWO rows sharing every weight load; accumulators packed over outputs.
template<int IN, int OUT, int ACT>
__device__ __forceinline__ void layer2(const float* __restrict__ Wt,
                                       const float* __restrict__ B,
                                       const float* in0, const float* in1,
                                       float* out0, float* out1) {
    u64 acc0[OUT / 2], acc1[OUT / 2];
#pragma unroll
    for (int o = 0; o < OUT / 2; o++) {
        u64 b = *reinterpret_cast<const u64*>(B + 2 * o);
        acc0[o] = b; acc1[o] = b;
    }
#pragma unroll
    for (int i = 0; i < IN; i++) {
        const u64 x0 = pk2(in0[i]);
        const u64 x1 = pk2(in1[i]);
#pragma unroll
        for (int o = 0; o < OUT / 2; o += 2) {
            ulonglong2 w = *reinterpret_cast<const ulonglong2*>(Wt + i * OUT + 2 * o);
            acc0[o]     = f2fma(w.x, x0, acc0[o]);
            acc1[o]     = f2fma(w.x, x1, acc1[o]);
            acc0[o + 1] = f2fma(w.y, x0, acc0[o + 1]);
            acc1[o + 1] = f2fma(w.y, x1, acc1[o + 1]);
        }
    }
#pragma unroll
    for (int o = 0; o < OUT / 2; o++) {
        float a, b, c, d;
        upk(a, b, acc0[o]); upk(c, d, acc1[o]);
        if (ACT == 1) {
            a = fmaxf(a, 0.0f); b = fmaxf(b, 0.0f);
            c = fmaxf(c, 0.0f); d = fmaxf(d, 0.0f);
        }
        if (ACT == 2) {
            a = fast_tanh(a); b = fast_tanh(b);
            c = fast_tanh(c); d = fast_tanh(d);
        }
        out0[2 * o] = a; out0[2 * o + 1] = b;
        out1[2 * o] = c; out1[2 * o + 1] = d;
    }
}

__device__ __forceinline__ float dot8(const float* __restrict__ W, float b,
                                      const float* in) {
    float4 w0 = *reinterpret_cast<const float4*>(W);
    float4 w1 = *reinterpret_cast<const float4*>(W + 4);
    float a = b;
    a = fmaf(w0.x, in[0], a); a = fmaf(w0.y, in[1], a);
    a = fmaf(w0.z, in[2], a); a = fmaf(w0.w, in[3], a);
    a = fmaf(w1.x, in[4], a); a = fmaf(w1.y, in[5], a);
    a = fmaf(w1.z, in[6], a); a = fmaf(w1.w, in[7], a);
    return a;
}

__device__ __forceinline__ void cpy(float* dst, const float* __restrict__ src,
                                    int n, int tid) {
    for (int i = tid; i < n; i += NTHREADS) dst[i] = src[i];
}

template<int IN, int OUT>
__device__ __forceinline__ void stage_t(float* dst, const float* __restrict__ src,
                                        int tid) {
    for (int idx = tid; idx < IN * OUT; idx += NTHREADS) {
        int i = idx / OUT;
        int o = idx & (OUT - 1);
        dst[idx] = src[o * IN + i];
    }
}

__global__ void __launch_bounds__(NTHREADS)
mlp32_kernel(const float* __restrict__ x,
             const float* __restrict__ Wa1, const float* __restrict__ ba1,
             const float* __restrict__ Wa2, const float* __restrict__ ba2,
             const float* __restrict__ Wa3, const float* __restrict__ ba3,
             const float* __restrict__ Wa4, const float* __restrict__ ba4,
             const float* __restrict__ Wa5, const float* __restrict__ ba5,
             const float* __restrict__ Wb1, const float* __restrict__ bb1,
             const float* __restrict__ Wb2, const float* __restrict__ bb2,
             const float* __restrict__ Wb3, const float* __restrict__ bb3,
             const float* __restrict__ Wb4, const float* __restrict__ bb4,
             const float* __restrict__ Wb5, const float* __restrict__ bb5,
             const float* __restrict__ Wb6, const float* __restrict__ bb6,
             float* __restrict__ out, int nrows) {
    __shared__ float s[SMEM_TOT];
    const int p = blockIdx.y;
    const int tid = threadIdx.x;

    // ---- stage weights (transposed) ----
    for (int idx = tid; idx < 32 * 64; idx += NTHREADS) {
        int i = idx >> 6, o = idx & 63;
        float v = 0.0f;
        if (i < p)      v = Wb1[(p * 64 + o) * 31 + i];
        else if (i > p) v = Wb1[(p * 64 + o) * 31 + i - 1];
        s[OFF_WB1T + idx] = v;
    }
    stage_t<64, 32>(s + OFF_WB2T, Wb2 + p * 32 * 64, tid);
    stage_t<32, 32>(s + OFF_WB3T, Wb3 + p * 32 * 32, tid);
    stage_t<32, 16>(s + OFF_WB4T, Wb4 + p * 16 * 32, tid);
    stage_t<16, 8>(s + OFF_WB5T, Wb5 + p * 8 * 16, tid);
    stage_t<64, 32>(s + OFF_WA2T, Wa2 + p * 32 * 64, tid);
    stage_t<32, 16>(s + OFF_WA3T, Wa3 + p * 16 * 32, tid);
    stage_t<16, 8>(s + OFF_WA4T, Wa4 + p * 8 * 16, tid);
    cpy(s + OFF_WA1, Wa1 + p * 64, 64, tid);
    cpy(s + OFF_BA1, ba1 + p * 64, 64, tid);
    cpy(s + OFF_BB1, bb1 + p * 64, 64, tid);
    cpy(s + OFF_BB2, bb2 + p * 32, 32, tid);
    cpy(s + OFF_BB3, bb3 + p * 32, 32, tid);
    cpy(s + OFF_BB4, bb4 + p * 16, 16, tid);
    cpy(s + OFF_BA2, ba2 + p * 32, 32, tid);
    cpy(s + OFF_BA3, ba3 + p * 16, 16, tid);
    cpy(s + OFF_BA4, ba4 + p * 8, 8, tid);
    cpy(s + OFF_BB5, bb5 + p * 8, 8, tid);
    cpy(s + OFF_WB6, Wb6 + p * 8, 8, tid);
    cpy(s + OFF_WA5, Wa5 + p * 8, 8, tid);
    if (tid == 0) {
        s[OFF_BB6] = bb6[p];
        s[OFF_BA5] = ba5[p];
    }
    __syncthreads();

    // each thread: RPT pairs of rows (row, row + NTHREADS)
    const int blockBase = blockIdx.x * (NTHREADS * 2 * RPT);

#pragma unroll 1
    for (int r = 0; r < RPT; ++r) {
        const int row0 = blockBase + r * (2 * NTHREADS) + tid;
        const int row1 = row0 + NTHREADS;
        if (row0 >= nrows) break;
        const bool has1 = (row1 < nrows);

        // load both rows of x (coalesced float4)
        float xr0[32], xr1[32];
        {
            const float4* xv0 = reinterpret_cast<const float4*>(x) + row0 * 8;
#pragma unroll
            for (int q = 0; q < 8; q++) {
                float4 v = xv0[q];
                xr0[4 * q] = v.x; xr0[4 * q + 1] = v.y;
                xr0[4 * q + 2] = v.z; xr0[4 * q + 3] = v.w;
            }
            if (has1) {
                const float4* xv1 = reinterpret_cast<const float4*>(x) + row1 * 8;
#pragma unroll
                for (int q = 0; q < 8; q++) {
                    float4 v = xv1[q];
                    xr1[4 * q] = v.x; xr1[4 * q + 1] = v.y;
                    xr1[4 * q + 2] = v.z; xr1[4 * q + 3] = v.w;
                }
            } else {
#pragma unroll
                for (int q = 0; q < 32; q++) xr1[q] = 0.0f;
            }
        }
        const float xs0 = x[row0 * 32 + p];
        const float xs1 = has1 ? x[row1 * 32 + p] : 0.0f;

        // ---- encoder B ----
        float h1a[64], h1b[64];
        layer2<32, 64, 1>(s + OFF_WB1T, s + OFF_BB1, xr0, xr1, h1a, h1b);
        float h2a[32], h2b[32];
        layer2<64, 32, 2>(s + OFF_WB2T, s + OFF_BB2, h1a, h1b, h2a, h2b);
        float h3a[32], h3b[32];
        layer2<32, 32, 2>(s + OFF_WB3T, s + OFF_BB3, h2a, h2b, h3a, h3b);
        float h4a[16], h4b[16];
        layer2<32, 16, 2>(s + OFF_WB4T, s + OFF_BB4, h3a, h3b, h4a, h4b);
        float h5a[8], h5b[8];
        layer2<16, 8, 0>(s + OFF_WB5T, s + OFF_BB5, h4a, h4b, h5a, h5b);
        const float bOut0 = dot8(s + OFF_WB6, s[OFF_BB6], h5a);
        const float bOut1 = dot8(s + OFF_WB6, s[OFF_BB6], h5b);

        // ---- encoder A: elementwise first layer (packed over outputs) ----
        float a1a[64], a1b[64];
        {
            const u64 xp0 = pk2(xs0), xp1 = pk2(xs1);
#pragma unroll
            for (int o = 0; o < 32; o += 2) {
                ulonglong2 w = *reinterpret_cast<const ulonglong2*>(s + OFF_WA1 + 2 * o);
                ulonglong2 bb = *reinterpret_cast<const ulonglong2*>(s + OFF_BA1 + 2 * o);
                u64 m0 = f2fma(w.x, xp0, bb.x);
                u64 m1 = f2fma(w.y, xp0, bb.y);
                u64 n0 = f2fma(w.x, xp1, bb.x);
                u64 n1 = f2fma(w.y, xp1, bb.y);
                float e, f, g, h;
                upk(e, f, m0); upk(g, h, m1);
                a1a[2 * o] = fmaxf(e, 0.0f); a1a[2 * o + 1] = fmaxf(f, 0.0f);
                a1a[2 * o + 2] = fmaxf(g, 0.0f); a1a[2 * o + 3] = fmaxf(h, 0.0f);
                upk(e, f, n0); upk(g, h, n1);
                a1b[2 * o] = fmaxf(e, 0.0f); a1b[2 * o + 1] = fmaxf(f, 0.0f);
                a1b[2 * o + 2] = fmaxf(g, 0.0f); a1b[2 * o + 3] = fmaxf(h, 0.0f);
            }
        }
        float a2a[32], a2b[32];
        layer2<64, 32, 2>(s + OFF_WA2T, s + OFF_BA2, a1a, a1b, a2a, a2b);
        float a3a[16], a3b[16];
        layer2<32, 16, 2>(s + OFF_WA3T, s + OFF_BA3, a2a, a2b, a3a, a3b);
        float a4a[8], a4b[8];
        layer2<16, 8, 2>(s + OFF_WA4T, s + OFF_BA4, a3a, a3b, a4a, a4b);
        const float aOut0 = dot8(s + OFF_WA5, s[OFF_BA5], a4a);
        const float aOut1 = dot8(s + OFF_WA5, s[OFF_BA5], a4b);

        out[row0 * 64 + 2 * p + 0] = aOut0;
        out[row0 * 64 + 2 * p + 1] = bOut0;
        if (has1) {
            out[row1 * 64 + 2 * p + 0] = aOut1;
            out[row1 * 64 + 2 * p + 1] = bOut1;
        }
    }
}

extern "C" void kernel_launch(void* const* d_in, const int* in_sizes, int n_in,
                              void* d_out, int out_size) {
    const float* x   = (const float*)d_in[0];
    const float* Wa1 = (const float*)d_in[1];
    const float* ba1 = (const float*)d_in[2];
    const float* Wa2 = (const float*)d_in[3];
    const float* ba2 = (const float*)d_in[4];
    const float* Wa3 = (const float*)d_in[5];
    const float* ba3 = (const float*)d_in[6];
    const float* Wa4 = (const float*)d_in[7];
    const float* ba4 = (const float*)d_in[8];
    const float* Wa5 = (const float*)d_in[9];
    const float* ba5 = (const float*)d_in[10];
    const float* Wb1 = (const float*)d_in[11];
    const float* bb1 = (const float*)d_in[12];
    const float* Wb2 = (const float*)d_in[13];
    const float* bb2 = (const float*)d_in[14];
    const float* Wb3 = (const float*)d_in[15];
    const float* bb3 = (const float*)d_in[16];
    const float* Wb4 = (const float*)d_in[17];
    const float* bb4 = (const float*)d_in[18];
    const float* Wb5 = (const float*)d_in[19];
    const float* bb5 = (const float*)d_in[20];
    const float* Wb6 = (const float*)d_in[21];
    const float* bb6 = (const float*)d_in[22];
    float* out = (float*)d_out;

    const int nrows = in_sizes[0] / PFEAT;
    const int rowsPerBlock = NTHREADS * 2 * RPT;
    dim3 grid((nrows + rowsPerBlock - 1) / rowsPerBlock, PFEAT);
    mlp32_kernel<<<grid, NTHREADS>>>(
        x, Wa1, ba1, Wa2, ba2, Wa3, ba3, Wa4, ba4, Wa5, ba5,
        Wb1, bb1, Wb2, bb2, Wb3, bb3, Wb4, bb4, Wb5, bb5, Wb6, bb6,
        out, nrows);
}

// round 4
// speedup vs baseline: 2.3587x; 1.3261x over previous
#include <cuda_runtime.h>
#include <cuda_bf16.h>
#include <cstdint>

#define NTHREADS 128
#define RPT 2
#define PFEAT 32

typedef unsigned long long u64;

// ---- shared-memory layout (floats); weight bases 16B-aligned ----
#define OFF_WB1T 0        // [32][64] (input-row p zeroed)
#define OFF_WB2T 2048     // [64][32]
#define OFF_WB3T 4096     // [32][32]
#define OFF_WB4T 5120     // [32][16]
#define OFF_WB5T 5632     // [16][8]
#define OFF_WA2T 5760     // [64][32]
#define OFF_WA3T 7808     // [32][16]
#define OFF_WA4T 8320     // [16][8]
#define OFF_WA1  8448     // 64
#define OFF_BA1  8512     // 64
#define OFF_BB1  8576     // 64
#define OFF_BB2  8640     // 32
#define OFF_BB3  8672     // 32
#define OFF_BB4  8704     // 16
#define OFF_BA2  8720     // 32
#define OFF_BA3  8752     // 16
#define OFF_BA4  8768     // 8
#define OFF_BB5  8776     // 8
#define OFF_WB6  8784     // 8
#define OFF_WA5  8792     // 8
#define OFF_BB6  8800     // 1
#define OFF_BA5  8804     // 1
#define SMEM_TOT 8808

// ---- f32x2 packed helpers ----
__device__ __forceinline__ u64 pk2(float v) {
    u64 r; asm("mov.b64 %0, {%1, %1};" : "=l"(r) : "f"(v)); return r;
}
__device__ __forceinline__ void upk(float& lo, float& hi, u64 v) {
    asm("mov.b64 {%0, %1}, %2;" : "=f"(lo), "=f"(hi) : "l"(v));
}
__device__ __forceinline__ u64 f2fma(u64 a, u64 b, u64 c) {
    u64 d; asm("fma.rn.f32x2 %0, %1, %2, %3;" : "=l"(d) : "l"(a), "l"(b), "l"(c));
    return d;
}

__device__ __forceinline__ float fast_tanh(float x) {
    float r; asm("tanh.approx.f32 %0, %1;" : "=f"(r) : "f"(x)); return r;
}

// ===== plain packed layer (2 rows share weights); ACT: 0 none, 2 tanh =====
template<int IN, int OUT, int ACT>
__device__ __forceinline__ void layer2(const float* __restrict__ Wt,
                                       const float* __restrict__ B,
                                       const float* in0, const float* in1,
                                       float* out0, float* out1) {
    u64 acc0[OUT / 2], acc1[OUT / 2];
#pragma unroll
    for (int o = 0; o < OUT / 2; o++) {
        u64 b = *reinterpret_cast<const u64*>(B + 2 * o);
        acc0[o] = b; acc1[o] = b;
    }
#pragma unroll
    for (int i = 0; i < IN; i++) {
        const u64 x0 = pk2(in0[i]);
        const u64 x1 = pk2(in1[i]);
#pragma unroll
        for (int o = 0; o < OUT / 2; o += 2) {
            ulonglong2 w = *reinterpret_cast<const ulonglong2*>(Wt + i * OUT + 2 * o);
            acc0[o]     = f2fma(w.x, x0, acc0[o]);
            acc1[o]     = f2fma(w.x, x1, acc1[o]);
            acc0[o + 1] = f2fma(w.y, x0, acc0[o + 1]);
            acc1[o + 1] = f2fma(w.y, x1, acc1[o + 1]);
        }
    }
#pragma unroll
    for (int o = 0; o < OUT / 2; o++) {
        float a, b, c, d;
        upk(a, b, acc0[o]); upk(c, d, acc1[o]);
        if (ACT == 2) { a = fast_tanh(a); b = fast_tanh(b); c = fast_tanh(c); d = fast_tanh(d); }
        out0[2 * o] = a; out0[2 * o + 1] = b;
        out1[2 * o] = c; out1[2 * o + 1] = d;
    }
}

// ===== fused: layer1 (IN1->MID, relu) streamed in CHUNKs into layer2 acc =====
// acc2_* must be pre-initialized with layer-2 bias. Wt1 [IN1][MID], Wt2 [MID][OUT2].
template<int IN1, int MID, int OUT2, int CHUNK>
__device__ __forceinline__ void fusedB(const float* __restrict__ Wt1,
                                       const float* __restrict__ B1,
                                       const float* __restrict__ Wt2,
                                       const float* in0, const float* in1,
                                       u64* acc2_0, u64* acc2_1) {
#pragma unroll
    for (int c = 0; c < MID; c += CHUNK) {
        u64 m0[CHUNK / 2], m1[CHUNK / 2];
#pragma unroll
        for (int j = 0; j < CHUNK / 2; j++) {
            u64 b = *reinterpret_cast<const u64*>(B1 + c + 2 * j);
            m0[j] = b; m1[j] = b;
        }
#pragma unroll
        for (int i = 0; i < IN1; i++) {
            const u64 x0 = pk2(in0[i]);
            const u64 x1 = pk2(in1[i]);
#pragma unroll
            for (int j = 0; j < CHUNK / 2; j += 2) {
                ulonglong2 w = *reinterpret_cast<const ulonglong2*>(Wt1 + i * MID + c + 2 * j);
                m0[j]     = f2fma(w.x, x0, m0[j]);
                m1[j]     = f2fma(w.x, x1, m1[j]);
                m0[j + 1] = f2fma(w.y, x0, m0[j + 1]);
                m1[j + 1] = f2fma(w.y, x1, m1[j + 1]);
            }
        }
        // relu chunk, accumulate into layer-2 accumulators
#pragma unroll
        for (int j = 0; j < CHUNK / 2; j++) {
            float e, f, g, h;
            upk(e, f, m0[j]); upk(g, h, m1[j]);
            e = fmaxf(e, 0.0f); f = fmaxf(f, 0.0f);
            g = fmaxf(g, 0.0f); h = fmaxf(h, 0.0f);
            const u64 p0 = pk2(e), p1 = pk2(f);
            const u64 q0 = pk2(g), q1 = pk2(h);
            const float* w2a = Wt2 + (c + 2 * j) * OUT2;
            const float* w2b = w2a + OUT2;
#pragma unroll
            for (int o = 0; o < OUT2 / 2; o += 2) {
                ulonglong2 wa = *reinterpret_cast<const ulonglong2*>(w2a + 2 * o);
                acc2_0[o]     = f2fma(wa.x, p0, acc2_0[o]);
                acc2_1[o]     = f2fma(wa.x, q0, acc2_1[o]);
                acc2_0[o + 1] = f2fma(wa.y, p0, acc2_0[o + 1]);
                acc2_1[o + 1] = f2fma(wa.y, q0, acc2_1[o + 1]);
                ulonglong2 wb = *reinterpret_cast<const ulonglong2*>(w2b + 2 * o);
                acc2_0[o]     = f2fma(wb.x, p1, acc2_0[o]);
                acc2_1[o]     = f2fma(wb.x, q1, acc2_1[o]);
                acc2_0[o + 1] = f2fma(wb.y, p1, acc2_0[o + 1]);
                acc2_1[o + 1] = f2fma(wb.y, q1, acc2_1[o + 1]);
            }
        }
    }
}

// ===== fused encoder-A head: elementwise (w*xs+b, relu) -> layer2 acc =====
template<int MID, int OUT2, int CHUNK>
__device__ __forceinline__ void fusedA(const float* __restrict__ W1,
                                       const float* __restrict__ B1,
                                       const float* __restrict__ Wt2,
                                       u64 xs0p, u64 xs1p,
                                       u64* acc2_0, u64* acc2_1) {
#pragma unroll
    for (int c = 0; c < MID; c += CHUNK) {
#pragma unroll
        for (int j = 0; j < CHUNK / 2; j++) {
            u64 w = *reinterpret_cast<const u64*>(W1 + c + 2 * j);
            u64 b = *reinterpret_cast<const u64*>(B1 + c + 2 * j);
            u64 m0 = f2fma(w, xs0p, b);
            u64 m1 = f2fma(w, xs1p, b);
            float e, f, g, h;
            upk(e, f, m0); upk(g, h, m1);
            e = fmaxf(e, 0.0f); f = fmaxf(f, 0.0f);
            g = fmaxf(g, 0.0f); h = fmaxf(h, 0.0f);
            const u64 p0 = pk2(e), p1 = pk2(f);
            const u64 q0 = pk2(g), q1 = pk2(h);
            const float* w2a = Wt2 + (c + 2 * j) * OUT2;
            const float* w2b = w2a + OUT2;
#pragma unroll
            for (int o = 0; o < OUT2 / 2; o += 2) {
                ulonglong2 wa = *reinterpret_cast<const ulonglong2*>(w2a + 2 * o);
                acc2_0[o]     = f2fma(wa.x, p0, acc2_0[o]);
                acc2_1[o]     = f2fma(wa.x, q0, acc2_1[o]);
                acc2_0[o + 1] = f2fma(wa.y, p0, acc2_0[o + 1]);
                acc2_1[o + 1] = f2fma(wa.y, q0, acc2_1[o + 1]);
                ulonglong2 wb = *reinterpret_cast<const ulonglong2*>(w2b + 2 * o);
                acc2_0[o]     = f2fma(wb.x, p1, acc2_0[o]);
                acc2_1[o]     = f2fma(wb.x, q1, acc2_1[o]);
                acc2_0[o + 1] = f2fma(wb.y, p1, acc2_0[o + 1]);
                acc2_1[o + 1] = f2fma(wb.y, q1, acc2_1[o + 1]);
            }
        }
    }
}

__device__ __forceinline__ float dot8(const float* __restrict__ W, float b,
                                      const float* in) {
    float4 w0 = *reinterpret_cast<const float4*>(W);
    float4 w1 = *reinterpret_cast<const float4*>(W + 4);
    float a = b;
    a = fmaf(w0.x, in[0], a); a = fmaf(w0.y, in[1], a);
    a = fmaf(w0.z, in[2], a); a = fmaf(w0.w, in[3], a);
    a = fmaf(w1.x, in[4], a); a = fmaf(w1.y, in[5], a);
    a = fmaf(w1.z, in[6], a); a = fmaf(w1.w, in[7], a);
    return a;
}

__device__ __forceinline__ void cpy(float* dst, const float* __restrict__ src,
                                    int n, int tid) {
    for (int i = tid; i < n; i += NTHREADS) dst[i] = src[i];
}

template<int IN, int OUT>
__device__ __forceinline__ void stage_t(float* dst, const float* __restrict__ src,
                                        int tid) {
    for (int idx = tid; idx < IN * OUT; idx += NTHREADS) {
        int i = idx / OUT;
        int o = idx & (OUT - 1);
        dst[idx] = src[o * IN + i];
    }
}

__global__ void __launch_bounds__(NTHREADS, 3)
mlp32_kernel(const float* __restrict__ x,
             const float* __restrict__ Wa1, const float* __restrict__ ba1,
             const float* __restrict__ Wa2, const float* __restrict__ ba2,
             const float* __restrict__ Wa3, const float* __restrict__ ba3,
             const float* __restrict__ Wa4, const float* __restrict__ ba4,
             const float* __restrict__ Wa5, const float* __restrict__ ba5,
             const float* __restrict__ Wb1, const float* __restrict__ bb1,
             const float* __restrict__ Wb2, const float* __restrict__ bb2,
             const float* __restrict__ Wb3, const float* __restrict__ bb3,
             const float* __restrict__ Wb4, const float* __restrict__ bb4,
             const float* __restrict__ Wb5, const float* __restrict__ bb5,
             const float* __restrict__ Wb6, const float* __restrict__ bb6,
             float* __restrict__ out, int nrows) {
    __shared__ float s[SMEM_TOT];
    const int p = blockIdx.y;
    const int tid = threadIdx.x;

    // ---- stage weights (transposed) ----
    for (int idx = tid; idx < 32 * 64; idx += NTHREADS) {
        int i = idx >> 6, o = idx & 63;
        float v = 0.0f;
        if (i < p)      v = Wb1[(p * 64 + o) * 31 + i];
        else if (i > p) v = Wb1[(p * 64 + o) * 31 + i - 1];
        s[OFF_WB1T + idx] = v;
    }
    stage_t<64, 32>(s + OFF_WB2T, Wb2 + p * 32 * 64, tid);
    stage_t<32, 32>(s + OFF_WB3T, Wb3 + p * 32 * 32, tid);
    stage_t<32, 16>(s + OFF_WB4T, Wb4 + p * 16 * 32, tid);
    stage_t<16, 8>(s + OFF_WB5T, Wb5 + p * 8 * 16, tid);
    stage_t<64, 32>(s + OFF_WA2T, Wa2 + p * 32 * 64, tid);
    stage_t<32, 16>(s + OFF_WA3T, Wa3 + p * 16 * 32, tid);
    stage_t<16, 8>(s + OFF_WA4T, Wa4 + p * 8 * 16, tid);
    cpy(s + OFF_WA1, Wa1 + p * 64, 64, tid);
    cpy(s + OFF_BA1, ba1 + p * 64, 64, tid);
    cpy(s + OFF_BB1, bb1 + p * 64, 64, tid);
    cpy(s + OFF_BB2, bb2 + p * 32, 32, tid);
    cpy(s + OFF_BB3, bb3 + p * 32, 32, tid);
    cpy(s + OFF_BB4, bb4 + p * 16, 16, tid);
    cpy(s + OFF_BA2, ba2 + p * 32, 32, tid);
    cpy(s + OFF_BA3, ba3 + p * 16, 16, tid);
    cpy(s + OFF_BA4, ba4 + p * 8, 8, tid);
    cpy(s + OFF_BB5, bb5 + p * 8, 8, tid);
    cpy(s + OFF_WB6, Wb6 + p * 8, 8, tid);
    cpy(s + OFF_WA5, Wa5 + p * 8, 8, tid);
    if (tid == 0) {
        s[OFF_BB6] = bb6[p];
        s[OFF_BA5] = ba5[p];
    }
    __syncthreads();

    const int blockBase = blockIdx.x * (NTHREADS * 2 * RPT);

#pragma unroll 1
    for (int r = 0; r < RPT; ++r) {
        const int row0 = blockBase + r * (2 * NTHREADS) + tid;
        const int row1 = row0 + NTHREADS;
        if (row0 >= nrows) break;
        const bool has1 = (row1 < nrows);

        float xr0[32], xr1[32];
        {
            const float4* xv0 = reinterpret_cast<const float4*>(x) + row0 * 8;
#pragma unroll
            for (int q = 0; q < 8; q++) {
                float4 v = xv0[q];
                xr0[4 * q] = v.x; xr0[4 * q + 1] = v.y;
                xr0[4 * q + 2] = v.z; xr0[4 * q + 3] = v.w;
            }
            if (has1) {
                const float4* xv1 = reinterpret_cast<const float4*>(x) + row1 * 8;
#pragma unroll
                for (int q = 0; q < 8; q++) {
                    float4 v = xv1[q];
                    xr1[4 * q] = v.x; xr1[4 * q + 1] = v.y;
                    xr1[4 * q + 2] = v.z; xr1[4 * q + 3] = v.w;
                }
            } else {
#pragma unroll
                for (int q = 0; q < 32; q++) xr1[q] = 0.0f;
            }
        }
        const float xs0 = xr0[p];
        const float xs1 = xr1[p];

        // ---- encoder B: fused (32->64 relu ->32 acc), tanh, 32->32, 32->16, 16->8, dot ----
        float h2a[32], h2b[32];
        {
            u64 acc0[16], acc1[16];
#pragma unroll
            for (int o = 0; o < 16; o++) {
                u64 b = *reinterpret_cast<const u64*>(s + OFF_BB2 + 2 * o);
                acc0[o] = b; acc1[o] = b;
            }
            fusedB<32, 64, 32, 8>(s + OFF_WB1T, s + OFF_BB1, s + OFF_WB2T,
                                  xr0, xr1, acc0, acc1);
#pragma unroll
            for (int o = 0; o < 16; o++) {
                float a, b, c, d;
                upk(a, b, acc0[o]); upk(c, d, acc1[o]);
                h2a[2 * o] = fast_tanh(a); h2a[2 * o + 1] = fast_tanh(b);
                h2b[2 * o] = fast_tanh(c); h2b[2 * o + 1] = fast_tanh(d);
            }
        }
        float h3a[32], h3b[32];
        layer2<32, 32, 2>(s + OFF_WB3T, s + OFF_BB3, h2a, h2b, h3a, h3b);
        float h4a[16], h4b[16];
        layer2<32, 16, 2>(s + OFF_WB4T, s + OFF_BB4, h3a, h3b, h4a, h4b);
        float h5a[8], h5b[8];
        layer2<16, 8, 0>(s + OFF_WB5T, s + OFF_BB5, h4a, h4b, h5a, h5b);
        const float bOut0 = dot8(s + OFF_WB6, s[OFF_BB6], h5a);
        const float bOut1 = dot8(s + OFF_WB6, s[OFF_BB6], h5b);

        // ---- encoder A: fused (1->64 relu ->32 acc), tanh, 32->16, 16->8, dot ----
        float a2a[32], a2b[32];
        {
            u64 acc0[16], acc1[16];
#pragma unroll
            for (int o = 0; o < 16; o++) {
                u64 b = *reinterpret_cast<const u64*>(s + OFF_BA2 + 2 * o);
                acc0[o] = b; acc1[o] = b;
            }
            fusedA<64, 32, 8>(s + OFF_WA1, s + OFF_BA1, s + OFF_WA2T,
                              pk2(xs0), pk2(xs1), acc0, acc1);
#pragma unroll
            for (int o = 0; o < 16; o++) {
                float a, b, c, d;
                upk(a, b, acc0[o]); upk(c, d, acc1[o]);
                a2a[2 * o] = fast_tanh(a); a2a[2 * o + 1] = fast_tanh(b);
                a2b[2 * o] = fast_tanh(c); a2b[2 * o + 1] = fast_tanh(d);
            }
        }
        float a3a[16], a3b[16];
        layer2<32, 16, 2>(s + OFF_WA3T, s + OFF_BA3, a2a, a2b, a3a, a3b);
        float a4a[8], a4b[8];
        layer2<16, 8, 2>(s + OFF_WA4T, s + OFF_BA4, a3a, a3b, a4a, a4b);
        const float aOut0 = dot8(s + OFF_WA5, s[OFF_BA5], a4a);
        const float aOut1 = dot8(s + OFF_WA5, s[OFF_BA5], a4b);

        out[row0 * 64 + 2 * p + 0] = aOut0;
        out[row0 * 64 + 2 * p + 1] = bOut0;
        if (has1) {
            out[row1 * 64 + 2 * p + 0] = aOut1;
            out[row1 * 64 + 2 * p + 1] = bOut1;
        }
    }
}

extern "C" void kernel_launch(void* const* d_in, const int* in_sizes, int n_in,
                              void* d_out, int out_size) {
    const float* x   = (const float*)d_in[0];
    const float* Wa1 = (const float*)d_in[1];
    const float* ba1 = (const float*)d_in[2];
    const float* Wa2 = (const float*)d_in[3];
    const float* ba2 = (const float*)d_in[4];
    const float* Wa3 = (const float*)d_in[5];
    const float* ba3 = (const float*)d_in[6];
    const float* Wa4 = (const float*)d_in[7];
    const float* ba4 = (const float*)d_in[8];
    const float* Wa5 = (const float*)d_in[9];
    const float* ba5 = (const float*)d_in[10];
    const float* Wb1 = (const float*)d_in[11];
    const float* bb1 = (const float*)d_in[12];
    const float* Wb2 = (const float*)d_in[13];
    const float* bb2 = (const float*)d_in[14];
    const float* Wb3 = (const float*)d_in[15];
    const float* bb3 = (const float*)d_in[16];
    const float* Wb4 = (const float*)d_in[17];
    const float* bb4 = (const float*)d_in[18];
    const float* Wb5 = (const float*)d_in[19];
    const float* bb5 = (const float*)d_in[20];
    const float* Wb6 = (const float*)d_in[21];
    const float* bb6 = (const float*)d_in[22];
    float* out = (float*)d_out;

    const int nrows = in_sizes[0] / PFEAT;
    const int rowsPerBlock = NTHREADS * 2 * RPT;
    dim3 grid((nrows + rowsPerBlock - 1) / rowsPerBlock, PFEAT);
    mlp32_kernel<<<grid, NTHREADS>>>(
        x, Wa1, ba1, Wa2, ba2, Wa3, ba3, Wa4, ba4, Wa5, ba5,
        Wb1, bb1, Wb2, bb2, Wb3, bb3, Wb4, bb4, Wb5, bb5, Wb6, bb6,
        out, nrows);
}